// round 14
// baseline (speedup 1.0000x reference)
#include <cuda_runtime.h>
#include <cuda_bf16.h>
#include <cstdint>

#define N 4096
#define C 64

// ---------------- scratch (device globals; no allocation) ----------------
__device__ __align__(1024) __nv_bfloat16 g_Qh2[2][N][64];   // hi-only, scaled log2e/8, [q][c]
__device__ __align__(1024) __nv_bfloat16 g_Kh2[2][N][64];   // hi-only, [k][c]
__device__ __align__(1024) float g_V[2][C * N];
__device__ __align__(1024) __nv_bfloat16 g_Vsb[4][C * N];   // V * (1/rowsum), bf16
__device__ float g_Prow[4][32][N];   // per-kblk partial sums (per query m)
__device__ __align__(1024) float g_P[4][C * N];  // message-passing output per mat
__device__ float g_Y[2][C * N];

// ---------------- helpers ----------------
__device__ __forceinline__ uint32_t smem_u32(const void* p) {
  uint32_t a;
  asm("{ .reg .u64 t; cvta.to.shared.u64 t, %1; cvt.u32.u64 %0, t; }" : "=r"(a) : "l"(p));
  return a;
}
__device__ __forceinline__ void cp16(uint32_t dst, const void* src) {
  asm volatile("cp.async.cg.shared.global [%0], [%1], 16;" :: "r"(dst), "l"(src) : "memory");
}
#define CP_COMMIT() asm volatile("cp.async.commit_group;" ::: "memory")
#define CP_WAIT(n_) asm volatile("cp.async.wait_group %0;" :: "n"(n_) : "memory")
// group-local barriers: producers (t<256) id 5, consumers (t>=256) id 6
#define BAR_PROD() asm volatile("bar.sync 5, 256;" ::: "memory")
#define BAR_CONS() asm volatile("bar.sync 6, 256;" ::: "memory")

__device__ __forceinline__ void mma16816(float* c, uint32_t a0, uint32_t a1, uint32_t a2,
                                         uint32_t a3, uint32_t b0, uint32_t b1) {
  asm volatile(
      "mma.sync.aligned.m16n8k16.row.col.f32.bf16.bf16.f32 "
      "{%0,%1,%2,%3}, {%4,%5,%6,%7}, {%8,%9}, {%0,%1,%2,%3};"
      : "+f"(c[0]), "+f"(c[1]), "+f"(c[2]), "+f"(c[3])
      : "r"(a0), "r"(a1), "r"(a2), "r"(a3), "r"(b0), "r"(b1));
}
__device__ __forceinline__ uint32_t packbf(float x, float y) {
  __nv_bfloat162 p = __halves2bfloat162(__float2bfloat16(x), __float2bfloat16(y));
  return *(uint32_t*)&p;
}
__device__ __forceinline__ float ex2(float x) {
  float y;
  asm("ex2.approx.ftz.f32 %0, %1;" : "=f"(y) : "f"(x));
  return y;
}

// producer (512-thr version): logits D[n][m] tile 64n x 32m (warp: n-half wn, m-quarter wm),
// ex2, stage bf16 [n][m] stride 136
__device__ __forceinline__ void produce_tile(const uint32_t* As, const uint32_t* Bs,
                                             __nv_bfloat16* stg, int wn, int wm,
                                             int r, int tq) {
  float acc[4][4][4];
#pragma unroll
  for (int i = 0; i < 4; i++)
#pragma unroll
    for (int j = 0; j < 4; j++)
#pragma unroll
      for (int v = 0; v < 4; v++) acc[i][j][v] = 0.f;
#pragma unroll
  for (int kf = 0; kf < 4; kf++) {
    int fo = kf * 8;
    uint32_t a[4][4], b[4][2];
#pragma unroll
    for (int nf = 0; nf < 4; nf++) {
      int row = wn * 64 + nf * 16 + r;
      a[nf][0] = As[row * 36 + fo + tq];
      a[nf][1] = As[(row + 8) * 36 + fo + tq];
      a[nf][2] = As[row * 36 + fo + tq + 4];
      a[nf][3] = As[(row + 8) * 36 + fo + tq + 4];
    }
#pragma unroll
    for (int mf = 0; mf < 4; mf++) {
      int mr = wm * 32 + mf * 8 + r;
      b[mf][0] = Bs[mr * 36 + fo + tq];
      b[mf][1] = Bs[mr * 36 + fo + tq + 4];
    }
#pragma unroll
    for (int nf = 0; nf < 4; nf++)
#pragma unroll
      for (int mf = 0; mf < 4; mf++)
        mma16816(acc[nf][mf], a[nf][0], a[nf][1], a[nf][2], a[nf][3], b[mf][0], b[mf][1]);
  }
#pragma unroll
  for (int i = 0; i < 4; i++)
#pragma unroll
    for (int j = 0; j < 4; j++)
#pragma unroll
      for (int v = 0; v < 4; v++) acc[i][j][v] = ex2(acc[i][j][v]);
#pragma unroll
  for (int nf = 0; nf < 4; nf++)
#pragma unroll
    for (int mf = 0; mf < 4; mf++) {
      int n = wn * 64 + nf * 16 + r;
      int m = wm * 32 + mf * 8 + 2 * tq;
      *(uint32_t*)&stg[n * 136 + m] = packbf(acc[nf][mf][0], acc[nf][mf][1]);
      *(uint32_t*)&stg[(n + 8) * 136 + m] = packbf(acc[nf][mf][2], acc[nf][mf][3]);
    }
}

// ---------------- K1: QKV projections (fp32 -> bf16 hi) ----------------
__global__ void __launch_bounds__(256) qkv_kernel(
    const float* __restrict__ Xi, const float* __restrict__ Xj,
    const float* __restrict__ Wq, const float* __restrict__ Wk, const float* __restrict__ Wv) {
  __shared__ float Xs[C][128];
  int side = blockIdx.y;
  const float* X = side ? Xj : Xi;
  int n0 = blockIdx.x * 128, t = threadIdx.x;
  for (int i = t; i < C * 32; i += 256) {
    int c = i >> 5, q = i & 31;
    *(float4*)&Xs[c][q * 4] = *(const float4*)&X[c * N + n0 + q * 4];
  }
  __syncthreads();
  int o = t & 63, g = t >> 6;
  float acc[32];
  {  // Q (scaled log2e/8)
#pragma unroll
    for (int k = 0; k < 32; k++) acc[k] = 0.f;
    for (int c = 0; c < C; c++) {
      float w = __ldg(&Wq[o * C + c]);
#pragma unroll
      for (int k = 0; k < 32; k++) acc[k] = fmaf(w, Xs[c][g + 4 * k], acc[k]);
    }
#pragma unroll
    for (int k = 0; k < 32; k++)
      g_Qh2[side][n0 + g + 4 * k][o] = __float2bfloat16(acc[k] * 0.1803368801111244f);
  }
  {  // K
#pragma unroll
    for (int k = 0; k < 32; k++) acc[k] = 0.f;
    for (int c = 0; c < C; c++) {
      float w = __ldg(&Wk[o * C + c]);
#pragma unroll
      for (int k = 0; k < 32; k++) acc[k] = fmaf(w, Xs[c][g + 4 * k], acc[k]);
    }
#pragma unroll
    for (int k = 0; k < 32; k++)
      g_Kh2[side][n0 + g + 4 * k][o] = __float2bfloat16(acc[k]);
  }
  {  // V fp32
#pragma unroll
    for (int k = 0; k < 32; k++) acc[k] = 0.f;
    for (int c = 0; c < C; c++) {
      float w = __ldg(&Wv[o * C + c]);
#pragma unroll
      for (int k = 0; k < 32; k++) acc[k] = fmaf(w, Xs[c][g + 4 * k], acc[k]);
    }
#pragma unroll
    for (int k = 0; k < 32; k++) g_V[side][o * N + n0 + g + 4 * k] = acc[k];
  }
}

// ---------------- K2 (pass 1): K=64 logits + ex2 + rowsum partials ----------------
__global__ void __launch_bounds__(256, 2) pass1_logits() {
  __shared__ __align__(16) char SM1[36864 + 1024];
  int t = threadIdx.x, lane = t & 31, wid = t >> 5;
  int wk = wid & 1, wq = wid >> 1;
  int r = lane >> 2, tq = lane & 3;
  int mat = blockIdx.z, kblk = blockIdx.x, qblk = blockIdx.y;
  int k0 = kblk * 128, q0 = qblk * 128;
  int qs = mat >> 1, ks = (mat == 1 || mat == 2) ? 1 : 0;
  const char* Ag = (const char*)&g_Kh2[ks][k0][0];
  const char* Bg = (const char*)&g_Qh2[qs][q0][0];
  char* Asm_ = SM1;
  char* Bsm_ = SM1 + 18432;

#pragma unroll
  for (int i = 0; i < 4; i++) {
    int idx = t + 256 * i, row = idx >> 3, c16 = idx & 7;
    cp16(smem_u32(Asm_ + row * 144 + c16 * 16), Ag + (size_t)row * 128 + c16 * 16);
    cp16(smem_u32(Bsm_ + row * 144 + c16 * 16), Bg + (size_t)row * 128 + c16 * 16);
  }
  CP_COMMIT();
  CP_WAIT(0);
  __syncthreads();

  float acc[4][4][4];
#pragma unroll
  for (int i = 0; i < 4; i++)
#pragma unroll
    for (int j = 0; j < 4; j++)
#pragma unroll
      for (int v = 0; v < 4; v++) acc[i][j][v] = 0.f;

  const uint32_t* As = (const uint32_t*)Asm_;
  const uint32_t* Bs = (const uint32_t*)Bsm_;
#pragma unroll
  for (int kf = 0; kf < 4; kf++) {
    int fo = kf * 8;
    uint32_t a[4][4], b[4][2];
#pragma unroll
    for (int nf = 0; nf < 4; nf++) {
      int row = wk * 64 + nf * 16 + r;
      a[nf][0] = As[row * 36 + fo + tq];
      a[nf][1] = As[(row + 8) * 36 + fo + tq];
      a[nf][2] = As[row * 36 + fo + tq + 4];
      a[nf][3] = As[(row + 8) * 36 + fo + tq + 4];
    }
#pragma unroll
    for (int qf = 0; qf < 4; qf++) {
      int qr = wq * 32 + qf * 8 + r;
      b[qf][0] = Bs[qr * 36 + fo + tq];
      b[qf][1] = Bs[qr * 36 + fo + tq + 4];
    }
#pragma unroll
    for (int nf = 0; nf < 4; nf++)
#pragma unroll
      for (int qf = 0; qf < 4; qf++)
        mma16816(acc[nf][qf], a[nf][0], a[nf][1], a[nf][2], a[nf][3], b[qf][0], b[qf][1]);
  }

#pragma unroll
  for (int kf = 0; kf < 4; kf++)
#pragma unroll
    for (int qf = 0; qf < 4; qf++)
#pragma unroll
      for (int v = 0; v < 4; v++) acc[kf][qf][v] = ex2(acc[kf][qf][v]);

  float colp[4][2];
#pragma unroll
  for (int qf = 0; qf < 4; qf++) {
    colp[qf][0] = colp[qf][1] = 0.f;
#pragma unroll
    for (int kf = 0; kf < 4; kf++) {
      colp[qf][0] += acc[kf][qf][0] + acc[kf][qf][2];
      colp[qf][1] += acc[kf][qf][1] + acc[kf][qf][3];
    }
    colp[qf][0] += __shfl_xor_sync(0xffffffffu, colp[qf][0], 4);
    colp[qf][0] += __shfl_xor_sync(0xffffffffu, colp[qf][0], 8);
    colp[qf][0] += __shfl_xor_sync(0xffffffffu, colp[qf][0], 16);
    colp[qf][1] += __shfl_xor_sync(0xffffffffu, colp[qf][1], 4);
    colp[qf][1] += __shfl_xor_sync(0xffffffffu, colp[qf][1], 8);
    colp[qf][1] += __shfl_xor_sync(0xffffffffu, colp[qf][1], 16);
  }
  float* colsum = (float*)(SM1 + 36864);
  if (lane < 4) {
#pragma unroll
    for (int qf = 0; qf < 4; qf++) {
      colsum[wk * 128 + wq * 32 + qf * 8 + 2 * tq + 0] = colp[qf][0];
      colsum[wk * 128 + wq * 32 + qf * 8 + 2 * tq + 1] = colp[qf][1];
    }
  }
  __syncthreads();
  if (t < 128) g_Prow[mat][kblk][q0 + t] = colsum[t] + colsum[128 + t];
}

// ---------------- K3: fused rowsum-reduce + V scale (bf16) ----------------
__global__ void __launch_bounds__(256) rsvscale_kernel() {
  __shared__ float rs_s[128];
  int mat = blockIdx.x >> 5, m0 = (blockIdx.x & 31) * 128;
  int t = threadIdx.x;
  if (t < 128) {
    float s = 0.f;
#pragma unroll
    for (int b = 0; b < 32; b++) s += g_Prow[mat][b][m0 + t];
    rs_s[t] = 1.0f / s;
  }
  __syncthreads();
  int c = t >> 2, g = t & 3;
  const float* Vp = &g_V[mat >> 1][c * N + m0 + g * 32];
  __nv_bfloat16* Op = &g_Vsb[mat][c * N + m0 + g * 32];
#pragma unroll
  for (int k = 0; k < 16; k++) {
    float v0 = Vp[2 * k] * rs_s[g * 32 + 2 * k];
    float v1 = Vp[2 * k + 1] * rs_s[g * 32 + 2 * k + 1];
    *(__nv_bfloat162*)&Op[2 * k] = __halves2bfloat162(__float2bfloat16(v0), __float2bfloat16(v1));
  }
}

// ---------------- K4 (pass 2): warp-specialized, 512 threads ----------------
// warps 0-7 (2/SMSP): logits(it+1) tiles + ex2 + stage slot (it+1)&1.
// warps 8-15 (2/SMSP): MP(it) from slot it&1 + V(it).
// One __syncthreads per iteration swaps slot ownership; group bar 5/6 fence cp.async.
__global__ void __launch_bounds__(512) fused_mp() {
  extern __shared__ __align__(16) char SM[];
  const int KRES = 0, QB = 18432, VBo = 73728, STG = 108544;  // Q:3x18432 V:2x17408 Stg:2x34816
  int t = threadIdx.x, lane = t & 31, wid = t >> 5;
  int r = lane >> 2, tq = lane & 3;
  int nblk = blockIdx.x, mat = blockIdx.y;
  int n0 = nblk * 128;
  int qs = mat >> 1, ks = (mat == 1 || mat == 2) ? 1 : 0;
  const char* Kg = (const char*)&g_Kh2[ks][n0][0];
  const char* Qg = (const char*)&g_Qh2[qs][0][0];
  const char* Vg = (const char*)&g_Vsb[mat][0];
  bool is_prod = (wid < 8);

  if (is_prod) {
    int wn = wid & 1, wm = wid >> 1;  // n-half, m-quarter
    // prologue: K + Q0 (group0), Q1 (group1); compute chunk0 -> slot0
#pragma unroll
    for (int i = 0; i < 4; i++) {
      int idx = t + 256 * i, row = idx >> 3, c16 = idx & 7;
      cp16(smem_u32(SM + KRES + row * 144 + c16 * 16), Kg + (size_t)row * 128 + c16 * 16);
      cp16(smem_u32(SM + QB + row * 144 + c16 * 16), Qg + (size_t)row * 128 + c16 * 16);
    }
    CP_COMMIT();
#pragma unroll
    for (int i = 0; i < 4; i++) {
      int idx = t + 256 * i, row = idx >> 3, c16 = idx & 7;
      cp16(smem_u32(SM + QB + 18432 + row * 144 + c16 * 16),
           Qg + (size_t)(128 + row) * 128 + c16 * 16);
    }
    CP_COMMIT();
    CP_WAIT(1);
    BAR_PROD();  // all producer warps' K+Q0 copies have landed
    produce_tile((const uint32_t*)(SM + KRES), (const uint32_t*)(SM + QB),
                 (__nv_bfloat16*)(SM + STG), wn, wm, r, tq);
  } else {
    // consumer prologue: V0 (group0)
    int tc = t - 256;
#pragma unroll
    for (int i = 0; i < 4; i++) {
      int idx = tc + 256 * i, row = idx >> 4, c16 = idx & 15;
      cp16(smem_u32(SM + VBo + row * 272 + c16 * 16), Vg + (size_t)row * N * 2 + c16 * 16);
    }
    CP_COMMIT();
  }
  __syncthreads();

  float accP[2][4][4];
#pragma unroll
  for (int i = 0; i < 2; i++)
#pragma unroll
    for (int j = 0; j < 4; j++)
#pragma unroll
      for (int v = 0; v < 4; v++) accP[i][j][v] = 0.f;

  for (int it = 0; it < 32; it++) {
    if (is_prod) {
      if (it < 31) {
        if (it + 2 < 32) {  // prefetch Q(it+2) into buffer (it+2)%3
          char* q = SM + QB + ((it + 2) % 3) * 18432;
          int m0 = (it + 2) * 128;
#pragma unroll
          for (int i = 0; i < 4; i++) {
            int idx = t + 256 * i, row = idx >> 3, c16 = idx & 7;
            cp16(smem_u32(q + row * 144 + c16 * 16), Qg + (size_t)(m0 + row) * 128 + c16 * 16);
          }
          CP_COMMIT();
        }
        if (it < 30) { CP_WAIT(1); } else { CP_WAIT(0); }
        BAR_PROD();  // sibling producers' Q(it+1) copies landed
        produce_tile((const uint32_t*)(SM + KRES),
                     (const uint32_t*)(SM + QB + ((it + 1) % 3) * 18432),
                     (__nv_bfloat16*)(SM + STG + ((it + 1) & 1) * 34816),
                     wid & 1, wid >> 1, r, tq);
      }
    } else {
      int tc = t - 256;
      if (it + 1 < 32) {  // prefetch V(it+1) into buffer (it+1)&1
        char* v = SM + VBo + ((it + 1) & 1) * 17408;
        int m0 = (it + 1) * 128;
#pragma unroll
        for (int i = 0; i < 4; i++) {
          int idx = tc + 256 * i, row = idx >> 4, c16 = idx & 15;
          cp16(smem_u32(v + row * 272 + c16 * 16), Vg + ((size_t)row * N + m0) * 2 + c16 * 16);
        }
        CP_COMMIT();
      }
      if (it < 31) { CP_WAIT(1); } else { CP_WAIT(0); }
      BAR_CONS();  // sibling consumers' V(it) copies landed
      // MP(it): slot it&1, V buffer it&1
      int wc = wid - 8, wcc = wc & 1, wnc = wc >> 1;  // ch-half, n-quarter
      const uint32_t* As2 = (const uint32_t*)(SM + VBo + (it & 1) * 17408);
      const uint32_t* Bs2 = (const uint32_t*)(SM + STG + (it & 1) * 34816);
#pragma unroll
      for (int kf = 0; kf < 8; kf++) {
        int fo = kf * 8;
        uint32_t a2[2][4], b2[4][2];
#pragma unroll
        for (int cf = 0; cf < 2; cf++) {
          int row = wcc * 32 + cf * 16 + r;
          a2[cf][0] = As2[row * 68 + fo + tq];
          a2[cf][1] = As2[(row + 8) * 68 + fo + tq];
          a2[cf][2] = As2[row * 68 + fo + tq + 4];
          a2[cf][3] = As2[(row + 8) * 68 + fo + tq + 4];
        }
#pragma unroll
        for (int nf2 = 0; nf2 < 4; nf2++) {
          int nr = wnc * 32 + nf2 * 8 + r;
          b2[nf2][0] = Bs2[nr * 68 + fo + tq];
          b2[nf2][1] = Bs2[nr * 68 + fo + tq + 4];
        }
#pragma unroll
        for (int cf = 0; cf < 2; cf++)
#pragma unroll
          for (int nf2 = 0; nf2 < 4; nf2++)
            mma16816(accP[cf][nf2], a2[cf][0], a2[cf][1], a2[cf][2], a2[cf][3],
                     b2[nf2][0], b2[nf2][1]);
      }
    }
    __syncthreads();
  }

  if (!is_prod) {
    int wc = wid - 8, wcc = wc & 1, wnc = wc >> 1;
#pragma unroll
    for (int cf = 0; cf < 2; cf++)
#pragma unroll
      for (int nf2 = 0; nf2 < 4; nf2++) {
        int ch = wcc * 32 + cf * 16 + r, n = wnc * 32 + nf2 * 8 + 2 * tq;
        *(float2*)&g_P[mat][ch * N + n0 + n] = make_float2(accP[cf][nf2][0], accP[cf][nf2][1]);
        *(float2*)&g_P[mat][(ch + 8) * N + n0 + n] = make_float2(accP[cf][nf2][2], accP[cf][nf2][3]);
      }
  }
}

// ---------------- K5: Y = Wp * (P0 + P1 + X) ----------------
__global__ void __launch_bounds__(256) ygemm_kernel(
    const float* __restrict__ Xi, const float* __restrict__ Xj,
    const float* __restrict__ Wpi, const float* __restrict__ Wpj) {
  __shared__ float Ts[C][128];
  __shared__ float Wsm[C][C];
  int pair = blockIdx.y;
  const float* X = pair ? Xj : Xi;
  const float* Wp = pair ? Wpj : Wpi;
  int n0 = blockIdx.x * 128, t = threadIdx.x;
  for (int i = t; i < C * C / 4; i += 256)
    *(float4*)&Wsm[0][i * 4] = *(const float4*)&Wp[i * 4];
  for (int i = t; i < C * 32; i += 256) {
    int c = i >> 5, q = i & 31;
    float4 v = *(const float4*)&X[c * N + n0 + q * 4];
    float4 p0 = *(const float4*)&g_P[2 * pair][c * N + n0 + q * 4];
    float4 p1 = *(const float4*)&g_P[2 * pair + 1][c * N + n0 + q * 4];
    v.x += p0.x + p1.x; v.y += p0.y + p1.y; v.z += p0.z + p1.z; v.w += p0.w + p1.w;
    *(float4*)&Ts[c][q * 4] = v;
  }
  __syncthreads();
  int n = t & 127, h = t >> 7;
  float acc[32];
#pragma unroll
  for (int oo = 0; oo < 32; oo++) acc[oo] = 0.f;
  for (int c = 0; c < C; c++) {
    float x = Ts[c][n];
#pragma unroll
    for (int oo = 0; oo < 32; oo++) acc[oo] = fmaf(Wsm[h * 32 + oo][c], x, acc[oo]);
  }
#pragma unroll
  for (int oo = 0; oo < 32; oo++) g_Y[pair][(h * 32 + oo) * N + n0 + n] = acc[oo];
}

// ---------------- K6: BN stats + LeakyReLU + sum (merged) ----------------
__global__ void __launch_bounds__(256) bn_epilogue_kernel(
    const float* __restrict__ gi, const float* __restrict__ bi,
    const float* __restrict__ gj, const float* __restrict__ bj,
    float* __restrict__ out) {
  int c = blockIdx.x, t = threadIdx.x;
  const float* y0 = &g_Y[0][c * N];
  const float* y1 = &g_Y[1][c * N];
  float s0 = 0.f, q0 = 0.f, s1 = 0.f, q1 = 0.f;
  for (int n = t; n < N; n += 256) {
    float v0 = y0[n], v1 = y1[n];
    s0 += v0; q0 += v0 * v0;
    s1 += v1; q1 += v1 * v1;
  }
  __shared__ float rs0[256], rq0[256], rs1[256], rq1[256];
  rs0[t] = s0; rq0[t] = q0; rs1[t] = s1; rq1[t] = q1;
  __syncthreads();
  for (int off = 128; off > 0; off >>= 1) {
    if (t < off) {
      rs0[t] += rs0[t + off]; rq0[t] += rq0[t + off];
      rs1[t] += rs1[t + off]; rq1[t] += rq1[t + off];
    }
    __syncthreads();
  }
  __shared__ float stat[4];
  if (t == 0) {
    float m0 = rs0[0] * (1.0f / N), m1 = rs1[0] * (1.0f / N);
    float v0 = rq0[0] * (1.0f / N) - m0 * m0;
    float v1 = rq1[0] * (1.0f / N) - m1 * m1;
    stat[0] = m0; stat[1] = rsqrtf(v0 + 1e-5f);
    stat[2] = m1; stat[3] = rsqrtf(v1 + 1e-5f);
  }
  __syncthreads();
  float m0 = stat[0], r0 = stat[1], m1 = stat[2], r1 = stat[3];
  float ga = gi[c], ba = bi[c], gb = gj[c], bb = bj[c];
  for (int n = t; n < N; n += 256) {
    float vi = (y0[n] - m0) * r0 * ga + ba;
    float vj = (y1[n] - m1) * r1 * gb + bb;
    vi = (vi >= 0.f) ? vi : 0.01f * vi;
    vj = (vj >= 0.f) ? vj : 0.01f * vj;
    out[c * N + n] = vi + vj;
  }
}

// ---------------- launch ----------------
extern "C" void kernel_launch(void* const* d_in, const int* in_sizes, int n_in,
                              void* d_out, int out_size) {
  const float* Xi = (const float*)d_in[0];
  const float* Xj = (const float*)d_in[1];
  const float* Wq = (const float*)d_in[2];
  const float* Wk = (const float*)d_in[3];
  const float* Wv = (const float*)d_in[4];
  const float* Wpi = (const float*)d_in[5];
  const float* Wpj = (const float*)d_in[6];
  const float* gi = (const float*)d_in[7];
  const float* bi = (const float*)d_in[8];
  const float* gj = (const float*)d_in[9];
  const float* bj = (const float*)d_in[10];
  float* out = (float*)d_out;

  cudaFuncSetAttribute(fused_mp, cudaFuncAttributeMaxDynamicSharedMemorySize, 178176);

  qkv_kernel<<<dim3(32, 2), 256>>>(Xi, Xj, Wq, Wk, Wv);
  pass1_logits<<<dim3(32, 32, 4), 256>>>();
  rsvscale_kernel<<<128, 256>>>();
  fused_mp<<<dim3(32, 4), 512, 178176>>>();
  ygemm_kernel<<<dim3(32, 2), 256>>>(Xi, Xj, Wpi, Wpj);
  bn_epilogue_kernel<<<64, 256>>>(gi, bi, gj, bj, out);
}

// round 15
// speedup vs baseline: 1.1690x; 1.1690x over previous
#include <cuda_runtime.h>
#include <cuda_bf16.h>
#include <cstdint>

#define N 4096
#define C 64

// ---------------- scratch (device globals; no allocation) ----------------
__device__ __align__(1024) __nv_bfloat16 g_Qh2[2][N][64];   // hi-only, scaled log2e/8, [q][c]
__device__ __align__(1024) __nv_bfloat16 g_Kh2[2][N][64];   // hi-only, [k][c]
__device__ __align__(1024) float g_V[2][C * N];
__device__ __align__(1024) __nv_bfloat16 g_Vsb[4][C * N];   // V * (1/rowsum), bf16
__device__ float g_Prow[4][32][N];   // per-kblk partial sums (per query m)
__device__ __align__(1024) float g_P[4][C * N];  // message-passing output per mat
__device__ float g_Y[2][C * N];

// ---------------- helpers ----------------
__device__ __forceinline__ uint32_t smem_u32(const void* p) {
  uint32_t a;
  asm("{ .reg .u64 t; cvta.to.shared.u64 t, %1; cvt.u32.u64 %0, t; }" : "=r"(a) : "l"(p));
  return a;
}
__device__ __forceinline__ void cp16(uint32_t dst, const void* src) {
  asm volatile("cp.async.cg.shared.global [%0], [%1], 16;" :: "r"(dst), "l"(src) : "memory");
}
#define CP_COMMIT() asm volatile("cp.async.commit_group;" ::: "memory")
#define CP_WAIT(n_) asm volatile("cp.async.wait_group %0;" :: "n"(n_) : "memory")
// group-local barriers for fused_mp: producers (warps 0-3) id 5, consumers (warps 4-7) id 6
#define BAR_PROD() asm volatile("bar.sync 5, 128;" ::: "memory")
#define BAR_CONS() asm volatile("bar.sync 6, 128;" ::: "memory")

__device__ __forceinline__ void mma16816(float* c, uint32_t a0, uint32_t a1, uint32_t a2,
                                         uint32_t a3, uint32_t b0, uint32_t b1) {
  asm volatile(
      "mma.sync.aligned.m16n8k16.row.col.f32.bf16.bf16.f32 "
      "{%0,%1,%2,%3}, {%4,%5,%6,%7}, {%8,%9}, {%0,%1,%2,%3};"
      : "+f"(c[0]), "+f"(c[1]), "+f"(c[2]), "+f"(c[3])
      : "r"(a0), "r"(a1), "r"(a2), "r"(a3), "r"(b0), "r"(b1));
}
__device__ __forceinline__ uint32_t packbf(float x, float y) {
  __nv_bfloat162 p = __halves2bfloat162(__float2bfloat16(x), __float2bfloat16(y));
  return *(uint32_t*)&p;
}
__device__ __forceinline__ float ex2(float x) {
  float y;
  asm("ex2.approx.ftz.f32 %0, %1;" : "=f"(y) : "f"(x));
  return y;
}

// producer: logits D[n][m] for one 128m chunk (warp: n-half wn, m-quarter wmp x h),
// ex2, stage bf16 [n][m] stride 136  (R13-proven)
__device__ __forceinline__ void produce_chunk(const uint32_t* As, const uint32_t* Bs,
                                              __nv_bfloat16* stg, int wn, int wmp,
                                              int r, int tq) {
#pragma unroll
  for (int h = 0; h < 2; h++) {
    float acc[4][4][4];
#pragma unroll
    for (int i = 0; i < 4; i++)
#pragma unroll
      for (int j = 0; j < 4; j++)
#pragma unroll
        for (int v = 0; v < 4; v++) acc[i][j][v] = 0.f;
#pragma unroll
    for (int kf = 0; kf < 4; kf++) {
      int fo = kf * 8;
      uint32_t a[4][4], b[4][2];
#pragma unroll
      for (int nf = 0; nf < 4; nf++) {
        int row = wn * 64 + nf * 16 + r;
        a[nf][0] = As[row * 36 + fo + tq];
        a[nf][1] = As[(row + 8) * 36 + fo + tq];
        a[nf][2] = As[row * 36 + fo + tq + 4];
        a[nf][3] = As[(row + 8) * 36 + fo + tq + 4];
      }
#pragma unroll
      for (int mf = 0; mf < 4; mf++) {
        int mr = h * 64 + wmp * 32 + mf * 8 + r;
        b[mf][0] = Bs[mr * 36 + fo + tq];
        b[mf][1] = Bs[mr * 36 + fo + tq + 4];
      }
#pragma unroll
      for (int nf = 0; nf < 4; nf++)
#pragma unroll
        for (int mf = 0; mf < 4; mf++)
          mma16816(acc[nf][mf], a[nf][0], a[nf][1], a[nf][2], a[nf][3], b[mf][0], b[mf][1]);
    }
#pragma unroll
    for (int i = 0; i < 4; i++)
#pragma unroll
      for (int j = 0; j < 4; j++)
#pragma unroll
        for (int v = 0; v < 4; v++) acc[i][j][v] = ex2(acc[i][j][v]);
#pragma unroll
    for (int nf = 0; nf < 4; nf++)
#pragma unroll
      for (int mf = 0; mf < 4; mf++) {
        int n = wn * 64 + nf * 16 + r;
        int m = h * 64 + wmp * 32 + mf * 8 + 2 * tq;
        *(uint32_t*)&stg[n * 136 + m] = packbf(acc[nf][mf][0], acc[nf][mf][1]);
        *(uint32_t*)&stg[(n + 8) * 136 + m] = packbf(acc[nf][mf][2], acc[nf][mf][3]);
      }
  }
}

// ---------------- K1: QKV projections (64-wide blocks, 128 CTAs) ----------------
__global__ void __launch_bounds__(256) qkv_kernel(
    const float* __restrict__ Xi, const float* __restrict__ Xj,
    const float* __restrict__ Wq, const float* __restrict__ Wk, const float* __restrict__ Wv) {
  __shared__ float Xs[C][64];
  int side = blockIdx.y;
  const float* X = side ? Xj : Xi;
  int n0 = blockIdx.x * 64, t = threadIdx.x;
  for (int i = t; i < C * 16; i += 256) {
    int c = i >> 4, q = i & 15;
    *(float4*)&Xs[c][q * 4] = *(const float4*)&X[c * N + n0 + q * 4];
  }
  __syncthreads();
  int o = t & 63, g = t >> 6;
  float acc[16];
  {  // Q (scaled log2e/8)
#pragma unroll
    for (int k = 0; k < 16; k++) acc[k] = 0.f;
    for (int c = 0; c < C; c++) {
      float w = __ldg(&Wq[o * C + c]);
#pragma unroll
      for (int k = 0; k < 16; k++) acc[k] = fmaf(w, Xs[c][g + 4 * k], acc[k]);
    }
#pragma unroll
    for (int k = 0; k < 16; k++)
      g_Qh2[side][n0 + g + 4 * k][o] = __float2bfloat16(acc[k] * 0.1803368801111244f);
  }
  {  // K
#pragma unroll
    for (int k = 0; k < 16; k++) acc[k] = 0.f;
    for (int c = 0; c < C; c++) {
      float w = __ldg(&Wk[o * C + c]);
#pragma unroll
      for (int k = 0; k < 16; k++) acc[k] = fmaf(w, Xs[c][g + 4 * k], acc[k]);
    }
#pragma unroll
    for (int k = 0; k < 16; k++)
      g_Kh2[side][n0 + g + 4 * k][o] = __float2bfloat16(acc[k]);
  }
  {  // V fp32
#pragma unroll
    for (int k = 0; k < 16; k++) acc[k] = 0.f;
    for (int c = 0; c < C; c++) {
      float w = __ldg(&Wv[o * C + c]);
#pragma unroll
      for (int k = 0; k < 16; k++) acc[k] = fmaf(w, Xs[c][g + 4 * k], acc[k]);
    }
#pragma unroll
    for (int k = 0; k < 16; k++) g_V[side][o * N + n0 + g + 4 * k] = acc[k];
  }
}

// ---------------- K2 (pass 1, persistent): K-tile resident, stream 32 Q chunks ----------------
// CTA = (mat, kblk): 128 CTAs. D[k][q] per chunk, ex2, column sums -> g_Prow[mat][kblk][q].
__global__ void __launch_bounds__(256) pass1_persist() {
  extern __shared__ __align__(16) char SMp[];
  const int AB = 0, QB = 18432, CS = 73728;  // A 18432, Q 3x18432, colsum 1024
  int t = threadIdx.x, lane = t & 31, wid = t >> 5;
  int wk = wid & 1, wq = wid >> 1;
  int r = lane >> 2, tq = lane & 3;
  int mat = blockIdx.x >> 5, kblk = blockIdx.x & 31;
  int k0 = kblk * 128;
  int qs = mat >> 1, ks = (mat == 1 || mat == 2) ? 1 : 0;
  const char* Ag = (const char*)&g_Kh2[ks][k0][0];
  const char* Qg = (const char*)&g_Qh2[qs][0][0];
  float* colsum = (float*)(SMp + CS);

  // prologue: A + Q0 (group0), Q1 (group1)
#pragma unroll
  for (int i = 0; i < 4; i++) {
    int idx = t + 256 * i, row = idx >> 3, c16 = idx & 7;
    cp16(smem_u32(SMp + AB + row * 144 + c16 * 16), Ag + (size_t)row * 128 + c16 * 16);
    cp16(smem_u32(SMp + QB + row * 144 + c16 * 16), Qg + (size_t)row * 128 + c16 * 16);
  }
  CP_COMMIT();
#pragma unroll
  for (int i = 0; i < 4; i++) {
    int idx = t + 256 * i, row = idx >> 3, c16 = idx & 7;
    cp16(smem_u32(SMp + QB + 18432 + row * 144 + c16 * 16),
         Qg + (size_t)(128 + row) * 128 + c16 * 16);
  }
  CP_COMMIT();

  const uint32_t* As = (const uint32_t*)(SMp + AB);
  for (int it = 0; it < 32; it++) {
    if (it + 2 < 32) {  // prefetch Q(it+2) into buffer (it+2)%3
      char* q = SMp + QB + ((it + 2) % 3) * 18432;
      int q0g = (it + 2) * 128;
#pragma unroll
      for (int i = 0; i < 4; i++) {
        int idx = t + 256 * i, row = idx >> 3, c16 = idx & 7;
        cp16(smem_u32(q + row * 144 + c16 * 16), Qg + (size_t)(q0g + row) * 128 + c16 * 16);
      }
      CP_COMMIT();
    }
    if (it < 30) { CP_WAIT(2); } else if (it == 30) { CP_WAIT(1); } else { CP_WAIT(0); }
    __syncthreads();  // all warps' copies for chunk(it) landed; colsum free

    const uint32_t* Bs = (const uint32_t*)(SMp + QB + (it % 3) * 18432);
    float acc[4][4][4];
#pragma unroll
    for (int i = 0; i < 4; i++)
#pragma unroll
      for (int j = 0; j < 4; j++)
#pragma unroll
        for (int v = 0; v < 4; v++) acc[i][j][v] = 0.f;
#pragma unroll
    for (int kf = 0; kf < 4; kf++) {
      int fo = kf * 8;
      uint32_t a[4][4], b[4][2];
#pragma unroll
      for (int nf = 0; nf < 4; nf++) {
        int row = wk * 64 + nf * 16 + r;
        a[nf][0] = As[row * 36 + fo + tq];
        a[nf][1] = As[(row + 8) * 36 + fo + tq];
        a[nf][2] = As[row * 36 + fo + tq + 4];
        a[nf][3] = As[(row + 8) * 36 + fo + tq + 4];
      }
#pragma unroll
      for (int qf = 0; qf < 4; qf++) {
        int qr = wq * 32 + qf * 8 + r;
        b[qf][0] = Bs[qr * 36 + fo + tq];
        b[qf][1] = Bs[qr * 36 + fo + tq + 4];
      }
#pragma unroll
      for (int nf = 0; nf < 4; nf++)
#pragma unroll
        for (int qf = 0; qf < 4; qf++)
          mma16816(acc[nf][qf], a[nf][0], a[nf][1], a[nf][2], a[nf][3], b[qf][0], b[qf][1]);
    }
#pragma unroll
    for (int kf = 0; kf < 4; kf++)
#pragma unroll
      for (int qf = 0; qf < 4; qf++)
#pragma unroll
        for (int v = 0; v < 4; v++) acc[kf][qf][v] = ex2(acc[kf][qf][v]);

    float colp[4][2];
#pragma unroll
    for (int qf = 0; qf < 4; qf++) {
      colp[qf][0] = colp[qf][1] = 0.f;
#pragma unroll
      for (int kf = 0; kf < 4; kf++) {
        colp[qf][0] += acc[kf][qf][0] + acc[kf][qf][2];
        colp[qf][1] += acc[kf][qf][1] + acc[kf][qf][3];
      }
      colp[qf][0] += __shfl_xor_sync(0xffffffffu, colp[qf][0], 4);
      colp[qf][0] += __shfl_xor_sync(0xffffffffu, colp[qf][0], 8);
      colp[qf][0] += __shfl_xor_sync(0xffffffffu, colp[qf][0], 16);
      colp[qf][1] += __shfl_xor_sync(0xffffffffu, colp[qf][1], 4);
      colp[qf][1] += __shfl_xor_sync(0xffffffffu, colp[qf][1], 8);
      colp[qf][1] += __shfl_xor_sync(0xffffffffu, colp[qf][1], 16);
    }
    if (lane < 4) {
#pragma unroll
      for (int qf = 0; qf < 4; qf++) {
        colsum[wk * 128 + wq * 32 + qf * 8 + 2 * tq + 0] = colp[qf][0];
        colsum[wk * 128 + wq * 32 + qf * 8 + 2 * tq + 1] = colp[qf][1];
      }
    }
    __syncthreads();
    if (t < 128) g_Prow[mat][kblk][it * 128 + t] = colsum[t] + colsum[128 + t];
  }
}

// ---------------- K3: fused rowsum-reduce + V scale (bf16) ----------------
__global__ void __launch_bounds__(256) rsvscale_kernel() {
  __shared__ float rs_s[128];
  int mat = blockIdx.x >> 5, m0 = (blockIdx.x & 31) * 128;
  int t = threadIdx.x;
  if (t < 128) {
    float s = 0.f;
#pragma unroll
    for (int b = 0; b < 32; b++) s += g_Prow[mat][b][m0 + t];
    rs_s[t] = 1.0f / s;
  }
  __syncthreads();
  int c = t >> 2, g = t & 3;
  const float* Vp = &g_V[mat >> 1][c * N + m0 + g * 32];
  __nv_bfloat16* Op = &g_Vsb[mat][c * N + m0 + g * 32];
#pragma unroll
  for (int k = 0; k < 16; k++) {
    float v0 = Vp[2 * k] * rs_s[g * 32 + 2 * k];
    float v1 = Vp[2 * k + 1] * rs_s[g * 32 + 2 * k + 1];
    *(__nv_bfloat162*)&Op[2 * k] = __halves2bfloat162(__float2bfloat16(v0), __float2bfloat16(v1));
  }
}

// ---------------- K4 (pass 2): warp-specialized (R13-proven) ----------------
__global__ void __launch_bounds__(256) fused_mp() {
  extern __shared__ __align__(16) char SM[];
  const int KRES = 0, QB = 18432, VBo = 73728, STG = 108544;  // Q:3x18432 V:2x17408 Stg:2x34816
  int t = threadIdx.x, lane = t & 31, wid = t >> 5;
  int r = lane >> 2, tq = lane & 3;
  int nblk = blockIdx.x, mat = blockIdx.y;
  int n0 = nblk * 128;
  int qs = mat >> 1, ks = (mat == 1 || mat == 2) ? 1 : 0;
  const char* Kg = (const char*)&g_Kh2[ks][n0][0];
  const char* Qg = (const char*)&g_Qh2[qs][0][0];
  const char* Vg = (const char*)&g_Vsb[mat][0];
  bool is_prod = (wid < 4);

  if (is_prod) {
#pragma unroll
    for (int i = 0; i < 8; i++) {
      int idx = t + 128 * i, row = idx >> 3, c16 = idx & 7;
      cp16(smem_u32(SM + KRES + row * 144 + c16 * 16), Kg + (size_t)row * 128 + c16 * 16);
      cp16(smem_u32(SM + QB + row * 144 + c16 * 16), Qg + (size_t)row * 128 + c16 * 16);
    }
    CP_COMMIT();
#pragma unroll
    for (int i = 0; i < 8; i++) {
      int idx = t + 128 * i, row = idx >> 3, c16 = idx & 7;
      cp16(smem_u32(SM + QB + 18432 + row * 144 + c16 * 16),
           Qg + (size_t)(128 + row) * 128 + c16 * 16);
    }
    CP_COMMIT();
    CP_WAIT(1);
    BAR_PROD();
    produce_chunk((const uint32_t*)(SM + KRES), (const uint32_t*)(SM + QB),
                  (__nv_bfloat16*)(SM + STG), wid & 1, wid >> 1, r, tq);
  } else {
    int tc = t - 128;
#pragma unroll
    for (int i = 0; i < 8; i++) {
      int idx = tc + 128 * i, row = idx >> 4, c16 = idx & 15;
      cp16(smem_u32(SM + VBo + row * 272 + c16 * 16), Vg + (size_t)row * N * 2 + c16 * 16);
    }
    CP_COMMIT();
  }
  __syncthreads();

  float accP[2][8][4];
#pragma unroll
  for (int i = 0; i < 2; i++)
#pragma unroll
    for (int j = 0; j < 8; j++)
#pragma unroll
      for (int v = 0; v < 4; v++) accP[i][j][v] = 0.f;

  for (int it = 0; it < 32; it++) {
    if (is_prod) {
      if (it < 31) {
        if (it + 2 < 32) {
          char* q = SM + QB + ((it + 2) % 3) * 18432;
          int m0 = (it + 2) * 128;
#pragma unroll
          for (int i = 0; i < 8; i++) {
            int idx = t + 128 * i, row = idx >> 3, c16 = idx & 7;
            cp16(smem_u32(q + row * 144 + c16 * 16), Qg + (size_t)(m0 + row) * 128 + c16 * 16);
          }
          CP_COMMIT();
        }
        if (it < 30) { CP_WAIT(1); } else { CP_WAIT(0); }
        BAR_PROD();
        produce_chunk((const uint32_t*)(SM + KRES),
                      (const uint32_t*)(SM + QB + ((it + 1) % 3) * 18432),
                      (__nv_bfloat16*)(SM + STG + ((it + 1) & 1) * 34816),
                      wid & 1, wid >> 1, r, tq);
      }
    } else {
      int tc = t - 128;
      if (it + 1 < 32) {
        char* v = SM + VBo + ((it + 1) & 1) * 17408;
        int m0 = (it + 1) * 128;
#pragma unroll
        for (int i = 0; i < 8; i++) {
          int idx = tc + 128 * i, row = idx >> 4, c16 = idx & 15;
          cp16(smem_u32(v + row * 272 + c16 * 16), Vg + ((size_t)row * N + m0) * 2 + c16 * 16);
        }
        CP_COMMIT();
      }
      if (it < 31) { CP_WAIT(1); } else { CP_WAIT(0); }
      BAR_CONS();
      int wc = wid - 4, wcc = wc & 1, wnc = wc >> 1;
      const uint32_t* As2 = (const uint32_t*)(SM + VBo + (it & 1) * 17408);
      const uint32_t* Bs2 = (const uint32_t*)(SM + STG + (it & 1) * 34816);
#pragma unroll
      for (int kf = 0; kf < 8; kf++) {
        int fo = kf * 8;
        uint32_t a2[2][4], b2[8][2];
#pragma unroll
        for (int cf = 0; cf < 2; cf++) {
          int row = wcc * 32 + cf * 16 + r;
          a2[cf][0] = As2[row * 68 + fo + tq];
          a2[cf][1] = As2[(row + 8) * 68 + fo + tq];
          a2[cf][2] = As2[row * 68 + fo + tq + 4];
          a2[cf][3] = As2[(row + 8) * 68 + fo + tq + 4];
        }
#pragma unroll
        for (int nf2 = 0; nf2 < 8; nf2++) {
          int nr = wnc * 64 + nf2 * 8 + r;
          b2[nf2][0] = Bs2[nr * 68 + fo + tq];
          b2[nf2][1] = Bs2[nr * 68 + fo + tq + 4];
        }
#pragma unroll
        for (int cf = 0; cf < 2; cf++)
#pragma unroll
          for (int nf2 = 0; nf2 < 8; nf2++)
            mma16816(accP[cf][nf2], a2[cf][0], a2[cf][1], a2[cf][2], a2[cf][3],
                     b2[nf2][0], b2[nf2][1]);
      }
    }
    __syncthreads();
  }

  if (!is_prod) {
    int wc = wid - 4, wcc = wc & 1, wnc = wc >> 1;
#pragma unroll
    for (int cf = 0; cf < 2; cf++)
#pragma unroll
      for (int nf2 = 0; nf2 < 8; nf2++) {
        int ch = wcc * 32 + cf * 16 + r, n = wnc * 64 + nf2 * 8 + 2 * tq;
        *(float2*)&g_P[mat][ch * N + n0 + n] = make_float2(accP[cf][nf2][0], accP[cf][nf2][1]);
        *(float2*)&g_P[mat][(ch + 8) * N + n0 + n] = make_float2(accP[cf][nf2][2], accP[cf][nf2][3]);
      }
  }
}

// ---------------- K5: Y = Wp * (P0 + P1 + X) (64-wide, 128 CTAs) ----------------
__global__ void __launch_bounds__(256) ygemm_kernel(
    const float* __restrict__ Xi, const float* __restrict__ Xj,
    const float* __restrict__ Wpi, const float* __restrict__ Wpj) {
  __shared__ float Ts[C][64];
  __shared__ float Wsm[C][C];
  int pair = blockIdx.y;
  const float* X = pair ? Xj : Xi;
  const float* Wp = pair ? Wpj : Wpi;
  int n0 = blockIdx.x * 64, t = threadIdx.x;
  for (int i = t; i < C * C / 4; i += 256)
    *(float4*)&Wsm[0][i * 4] = *(const float4*)&Wp[i * 4];
  for (int i = t; i < C * 16; i += 256) {
    int c = i >> 4, q = i & 15;
    float4 v = *(const float4*)&X[c * N + n0 + q * 4];
    float4 p0 = *(const float4*)&g_P[2 * pair][c * N + n0 + q * 4];
    float4 p1 = *(const float4*)&g_P[2 * pair + 1][c * N + n0 + q * 4];
    v.x += p0.x + p1.x; v.y += p0.y + p1.y; v.z += p0.z + p1.z; v.w += p0.w + p1.w;
    *(float4*)&Ts[c][q * 4] = v;
  }
  __syncthreads();
  int n = t & 63, h = t >> 6;  // h: 0..3 -> out channels h*16..h*16+15
  float acc[16];
#pragma unroll
  for (int oo = 0; oo < 16; oo++) acc[oo] = 0.f;
  for (int c = 0; c < C; c++) {
    float x = Ts[c][n];
#pragma unroll
    for (int oo = 0; oo < 16; oo++) acc[oo] = fmaf(Wsm[h * 16 + oo][c], x, acc[oo]);
  }
#pragma unroll
  for (int oo = 0; oo < 16; oo++) g_Y[pair][(h * 16 + oo) * N + n0 + n] = acc[oo];
}

// ---------------- K6: BN stats + LeakyReLU + sum (merged) ----------------
__global__ void __launch_bounds__(256) bn_epilogue_kernel(
    const float* __restrict__ gi, const float* __restrict__ bi,
    const float* __restrict__ gj, const float* __restrict__ bj,
    float* __restrict__ out) {
  int c = blockIdx.x, t = threadIdx.x;
  const float* y0 = &g_Y[0][c * N];
  const float* y1 = &g_Y[1][c * N];
  float s0 = 0.f, q0 = 0.f, s1 = 0.f, q1 = 0.f;
  for (int n = t; n < N; n += 256) {
    float v0 = y0[n], v1 = y1[n];
    s0 += v0; q0 += v0 * v0;
    s1 += v1; q1 += v1 * v1;
  }
  __shared__ float rs0[256], rq0[256], rs1[256], rq1[256];
  rs0[t] = s0; rq0[t] = q0; rs1[t] = s1; rq1[t] = q1;
  __syncthreads();
  for (int off = 128; off > 0; off >>= 1) {
    if (t < off) {
      rs0[t] += rs0[t + off]; rq0[t] += rq0[t + off];
      rs1[t] += rs1[t + off]; rq1[t] += rq1[t + off];
    }
    __syncthreads();
  }
  __shared__ float stat[4];
  if (t == 0) {
    float m0 = rs0[0] * (1.0f / N), m1 = rs1[0] * (1.0f / N);
    float v0 = rq0[0] * (1.0f / N) - m0 * m0;
    float v1 = rq1[0] * (1.0f / N) - m1 * m1;
    stat[0] = m0; stat[1] = rsqrtf(v0 + 1e-5f);
    stat[2] = m1; stat[3] = rsqrtf(v1 + 1e-5f);
  }
  __syncthreads();
  float m0 = stat[0], r0 = stat[1], m1 = stat[2], r1 = stat[3];
  float ga = gi[c], ba = bi[c], gb = gj[c], bb = bj[c];
  for (int n = t; n < N; n += 256) {
    float vi = (y0[n] - m0) * r0 * ga + ba;
    float vj = (y1[n] - m1) * r1 * gb + bb;
    vi = (vi >= 0.f) ? vi : 0.01f * vi;
    vj = (vj >= 0.f) ? vj : 0.01f * vj;
    out[c * N + n] = vi + vj;
  }
}

// ---------------- launch ----------------
extern "C" void kernel_launch(void* const* d_in, const int* in_sizes, int n_in,
                              void* d_out, int out_size) {
  const float* Xi = (const float*)d_in[0];
  const float* Xj = (const float*)d_in[1];
  const float* Wq = (const float*)d_in[2];
  const float* Wk = (const float*)d_in[3];
  const float* Wv = (const float*)d_in[4];
  const float* Wpi = (const float*)d_in[5];
  const float* Wpj = (const float*)d_in[6];
  const float* gi = (const float*)d_in[7];
  const float* bi = (const float*)d_in[8];
  const float* gj = (const float*)d_in[9];
  const float* bj = (const float*)d_in[10];
  float* out = (float*)d_out;

  cudaFuncSetAttribute(pass1_persist, cudaFuncAttributeMaxDynamicSharedMemorySize, 74752);
  cudaFuncSetAttribute(fused_mp, cudaFuncAttributeMaxDynamicSharedMemorySize, 178176);

  qkv_kernel<<<dim3(64, 2), 256>>>(Xi, Xj, Wq, Wk, Wv);
  pass1_persist<<<128, 256, 74752>>>();
  rsvscale_kernel<<<128, 256>>>();
  fused_mp<<<dim3(32, 4), 256, 178176>>>();
  ygemm_kernel<<<dim3(64, 2), 256>>>(Xi, Xj, Wpi, Wpj);
  bn_epilogue_kernel<<<64, 256>>>(gi, bi, gj, bj, out);
}